// round 5
// baseline (speedup 1.0000x reference)
#include <cuda_runtime.h>
#include <math.h>

// ---------------------------------------------------------------------------
// MDTA: x -> 1x1 conv (qkv) -> depthwise 3x3 (+fused L2 sumsq for q,k)
//       -> channel attention (48x48 per head) -> attn@v -> 1x1 proj
// Shapes: b=16, c=384, h=w=64 (hw=4096), heads=8, d=48, 3c=1152
// ---------------------------------------------------------------------------

#define B_   16
#define C_   384
#define C3_  1152
#define HW_  4096
#define NH_  8
#define DH_  48

// Scratch (device globals; no allocation allowed)
__device__ float g_qkv [(size_t)B_ * C3_ * HW_];   // after 1x1 conv
__device__ float g_qkvd[(size_t)B_ * C3_ * HW_];   // after depthwise 3x3
__device__ float g_invn[B_ * 2 * C_];              // 1/max(||row||,eps)
__device__ float g_aout[(size_t)B_ * C_ * HW_];    // attention output (b,c,hw)

// ---------------------------------------------------------------------------
// Batched SGEMM: C[b] (M x N) = A (M x K) @ B[b] (K x N), N = 4096, fp32.
// 128x128x8 tiles, 256 threads, 8x8 micro-tile in 2x2 blocks of 4 (bank-
// conflict-free LDS), double-buffered smem (1 barrier per k-tile) +
// register prefetch.  M%128==0, N%128==0, K%8==0.
// ---------------------------------------------------------------------------
__global__ __launch_bounds__(256) void gemm_batched(
    const float* __restrict__ A, const float* __restrict__ Bm,
    float* __restrict__ Cm, int M, int K)
{
    const int N = HW_;
    __shared__ float As[2][8][128];
    __shared__ float Bs[2][8][128];

    const int t  = threadIdx.x;
    const int tx = t & 15;          // 0..15
    const int ty = t >> 4;          // 0..15
    const int m0 = blockIdx.y * 128;
    const int n0 = blockIdx.x * 128;

    const float* Bb = Bm + (size_t)blockIdx.z * K * N;
    float*       Cb = Cm + (size_t)blockIdx.z * M * N;

    // A loader: thread t -> row (t>>1), k-quad ((t&1)*4)
    const int am  = t >> 1;
    const int ak4 = (t & 1) * 4;
    // B loader: thread t -> k-row (t>>5), n-quad ((t&31)*4)
    const int bk  = t >> 5;
    const int bn4 = (t & 31) * 4;

    const float* Aptr = A  + (size_t)(m0 + am) * K + ak4;
    const float* Bptr = Bb + (size_t)bk * N + n0 + bn4;

    float acc[8][8];
#pragma unroll
    for (int i = 0; i < 8; i++)
#pragma unroll
        for (int j = 0; j < 8; j++) acc[i][j] = 0.f;

    // prologue: load k-tile 0 into buffer 0
    {
        float4 av = *(const float4*)(Aptr);
        float4 bv = *(const float4*)(Bptr);
        As[0][ak4 + 0][am] = av.x;
        As[0][ak4 + 1][am] = av.y;
        As[0][ak4 + 2][am] = av.z;
        As[0][ak4 + 3][am] = av.w;
        *(float4*)&Bs[0][bk][bn4] = bv;
    }
    __syncthreads();

    int p = 0;
    for (int k0 = 0; k0 < K; k0 += 8) {
        const bool has_next = (k0 + 8 < K);
        float4 av, bv;
        if (has_next) {
            av = *(const float4*)(Aptr + k0 + 8);
            bv = *(const float4*)(Bptr + (size_t)(k0 + 8) * N);
        }

#pragma unroll
        for (int kk = 0; kk < 8; kk++) {
            float a[8], b[8];
            *(float4*)&a[0] = *(const float4*)&As[p][kk][ty * 4];
            *(float4*)&a[4] = *(const float4*)&As[p][kk][64 + ty * 4];
            *(float4*)&b[0] = *(const float4*)&Bs[p][kk][tx * 4];
            *(float4*)&b[4] = *(const float4*)&Bs[p][kk][64 + tx * 4];
#pragma unroll
            for (int i = 0; i < 8; i++)
#pragma unroll
                for (int j = 0; j < 8; j++)
                    acc[i][j] = fmaf(a[i], b[j], acc[i][j]);
        }

        if (has_next) {
            const int np = p ^ 1;
            As[np][ak4 + 0][am] = av.x;
            As[np][ak4 + 1][am] = av.y;
            As[np][ak4 + 2][am] = av.z;
            As[np][ak4 + 3][am] = av.w;
            *(float4*)&Bs[np][bk][bn4] = bv;
        }
        __syncthreads();
        p ^= 1;
    }

    // epilogue: rows {m0+ty*4+i, m0+64+ty*4+i}, cols {n0+tx*4, n0+64+tx*4}
#pragma unroll
    for (int blk = 0; blk < 2; blk++) {
#pragma unroll
        for (int i = 0; i < 4; i++) {
            int row = m0 + blk * 64 + ty * 4 + i;
            float* crow = &Cb[(size_t)row * N + n0];
            *(float4*)(crow + tx * 4) =
                make_float4(acc[blk*4+i][0], acc[blk*4+i][1],
                            acc[blk*4+i][2], acc[blk*4+i][3]);
            *(float4*)(crow + 64 + tx * 4) =
                make_float4(acc[blk*4+i][4], acc[blk*4+i][5],
                            acc[blk*4+i][6], acc[blk*4+i][7]);
        }
    }
}

// ---------------------------------------------------------------------------
// Depthwise 3x3 (SAME, groups=3c) fused with L2 sumsq for q/k channels.
// One block per (b,c) 64x64 plane; input plane + halo staged in smem.
// For channels c < 768 (q and k), also reduces sum(out^2) and writes
// invn[b*768+c] = 1/max(sqrt(ss), eps). grid = B_*C3_, 256 threads.
// ---------------------------------------------------------------------------
__global__ __launch_bounds__(256) void dwconv3x3_fused(
    const float* __restrict__ in, const float* __restrict__ wdw,
    float* __restrict__ out, float* __restrict__ invn)
{
    const int bc = blockIdx.x;            // b*1152 + c
    const int c  = bc % C3_;
    const int b  = bc / C3_;
    const int t  = threadIdx.x;

    __shared__ float tile[66 * 66];       // input plane with 1-px zero halo
    __shared__ float red[256];

    const float* ip = in  + ((size_t)bc << 12);
    float*       op = out + ((size_t)bc << 12);

    // stage 66x66 tile (zero-padded halo)
    for (int i = t; i < 66 * 66; i += 256) {
        int yy = i / 66 - 1;
        int xx = i % 66 - 1;
        float v = 0.f;
        if (yy >= 0 && yy < 64 && xx >= 0 && xx < 64)
            v = ip[yy * 64 + xx];
        tile[i] = v;
    }

    // weights for this channel
    float w0 = wdw[c * 9 + 0], w1 = wdw[c * 9 + 1], w2 = wdw[c * 9 + 2];
    float w3 = wdw[c * 9 + 3], w4 = wdw[c * 9 + 4], w5 = wdw[c * 9 + 5];
    float w6 = wdw[c * 9 + 6], w7 = wdw[c * 9 + 7], w8 = wdw[c * 9 + 8];

    __syncthreads();

    float ss = 0.f;
    // each thread: 16 pixels, strided
#pragma unroll
    for (int it = 0; it < 16; it++) {
        int pix = t + it * 256;
        int y = pix >> 6, x = pix & 63;
        const float* tp = &tile[y * 66 + x];   // == input (y-1, x-1)
        float s;
        s =          tp[0]        * w0;
        s = fmaf(tp[1],        w1, s);
        s = fmaf(tp[2],        w2, s);
        s = fmaf(tp[66],       w3, s);
        s = fmaf(tp[67],       w4, s);
        s = fmaf(tp[68],       w5, s);
        s = fmaf(tp[132],      w6, s);
        s = fmaf(tp[133],      w7, s);
        s = fmaf(tp[134],      w8, s);
        op[pix] = s;
        ss = fmaf(s, s, ss);
    }

    // only q (c<384) and k (384<=c<768) need norms
    if (c < 2 * C_) {
        red[t] = ss;
        __syncthreads();
        for (int o = 128; o > 0; o >>= 1) {
            if (t < o) red[t] += red[t + o];
            __syncthreads();
        }
        if (t == 0)
            invn[b * 768 + c] = 1.f / fmaxf(sqrtf(red[0]), 1e-12f);
    }
}

// ---------------------------------------------------------------------------
// Fused channel attention per (b, head): S = (qn @ knT) * temp; softmax rows;
// out = S @ v.  q,k,v rows are 4096 long, 48 rows each. Block = 256 threads.
// ---------------------------------------------------------------------------
__global__ __launch_bounds__(256) void attention(
    const float* __restrict__ qkvd, const float* __restrict__ invn,
    const float* __restrict__ temp, float* __restrict__ aout)
{
    const int bh = blockIdx.x;
    const int b  = bh >> 3;
    const int hd = bh & 7;

    const float* q = qkvd + ((size_t)b * C3_ +            hd * DH_) * HW_;
    const float* k = qkvd + ((size_t)b * C3_ + C_  +      hd * DH_) * HW_;
    const float* v = qkvd + ((size_t)b * C3_ + 2 * C_ +   hd * DH_) * HW_;
    float*       o = aout + ((size_t)b * C_  +            hd * DH_) * HW_;

    __shared__ float pool[2 * 64 * 49];      // qs/ks phase1, vs phase2
    __shared__ float S[DH_ * 49];            // scores / attn, padded rows

    float* qs = pool;                 // qs[n][d] = pool[n*49 + d]
    float* ks = pool + 64 * 49;

    const int t  = threadIdx.x;
    const int tx = t & 15;            // 16
    const int ty = t >> 4;            // 16

    // ---- phase 1: S[d][e] = sum_n q[d][n] k[e][n] ----
    float acc[3][3];
#pragma unroll
    for (int i = 0; i < 3; i++)
#pragma unroll
        for (int j = 0; j < 3; j++) acc[i][j] = 0.f;

    for (int n0 = 0; n0 < HW_; n0 += 64) {
        for (int i = t; i < DH_ * 64; i += 256) {
            int d = i >> 6, n = i & 63;
            qs[n * 49 + d] = q[(size_t)d * HW_ + n0 + n];
            ks[n * 49 + d] = k[(size_t)d * HW_ + n0 + n];
        }
        __syncthreads();
#pragma unroll 8
        for (int nn = 0; nn < 64; nn++) {
            float qa[3], kb[3];
#pragma unroll
            for (int i = 0; i < 3; i++) qa[i] = qs[nn * 49 + ty * 3 + i];
#pragma unroll
            for (int j = 0; j < 3; j++) kb[j] = ks[nn * 49 + tx * 3 + j];
#pragma unroll
            for (int i = 0; i < 3; i++)
#pragma unroll
                for (int j = 0; j < 3; j++) acc[i][j] = fmaf(qa[i], kb[j], acc[i][j]);
        }
        __syncthreads();
    }

    // scale by inverse norms and temperature, store to S
    {
        const float tval = temp[hd];
        const float* iq = invn + b * 768 + hd * DH_;
        const float* ik = invn + b * 768 + C_ + hd * DH_;
#pragma unroll
        for (int i = 0; i < 3; i++) {
            int d = ty * 3 + i;
#pragma unroll
            for (int j = 0; j < 3; j++) {
                int e = tx * 3 + j;
                S[d * 49 + e] = acc[i][j] * iq[d] * ik[e] * tval;
            }
        }
    }
    __syncthreads();

    // ---- softmax over e (rows of 48); thread d handles one row ----
    if (t < DH_) {
        float m = -1e30f;
#pragma unroll
        for (int e = 0; e < DH_; e++) m = fmaxf(m, S[t * 49 + e]);
        float sum = 0.f;
#pragma unroll
        for (int e = 0; e < DH_; e++) {
            float ex = expf(S[t * 49 + e] - m);
            S[t * 49 + e] = ex;
            sum += ex;
        }
        float inv = 1.f / sum;
#pragma unroll
        for (int e = 0; e < DH_; e++) S[t * 49 + e] *= inv;
    }
    __syncthreads();

    // ---- phase 2: out[d][n] = sum_e S[d][e] v[e][n] ----
    float* vs = pool;                 // vs[e][n] = pool[e*68 + n], 48x68
    for (int n0 = 0; n0 < HW_; n0 += 64) {
        for (int i = t; i < DH_ * 64; i += 256) {
            int e = i >> 6, n = i & 63;
            vs[e * 68 + n] = v[(size_t)e * HW_ + n0 + n];
        }
        __syncthreads();

        float acc2[3][4];
#pragma unroll
        for (int i = 0; i < 3; i++)
#pragma unroll
            for (int j = 0; j < 4; j++) acc2[i][j] = 0.f;

#pragma unroll 8
        for (int e = 0; e < DH_; e++) {
            float a0 = S[(ty * 3 + 0) * 49 + e];
            float a1 = S[(ty * 3 + 1) * 49 + e];
            float a2 = S[(ty * 3 + 2) * 49 + e];
            float4 vv = *(const float4*)&vs[e * 68 + tx * 4];
            float vb[4] = {vv.x, vv.y, vv.z, vv.w};
#pragma unroll
            for (int j = 0; j < 4; j++) {
                acc2[0][j] = fmaf(a0, vb[j], acc2[0][j]);
                acc2[1][j] = fmaf(a1, vb[j], acc2[1][j]);
                acc2[2][j] = fmaf(a2, vb[j], acc2[2][j]);
            }
        }
#pragma unroll
        for (int i = 0; i < 3; i++) {
            float4 cv = make_float4(acc2[i][0], acc2[i][1], acc2[i][2], acc2[i][3]);
            *(float4*)&o[(size_t)(ty * 3 + i) * HW_ + n0 + tx * 4] = cv;
        }
        __syncthreads();
    }
}

// ---------------------------------------------------------------------------
extern "C" void kernel_launch(void* const* d_in, const int* in_sizes, int n_in,
                              void* d_out, int out_size)
{
    const float* x      = (const float*)d_in[0];
    const float* w_qkv  = (const float*)d_in[1];
    const float* w_dw   = (const float*)d_in[2];
    const float* w_proj = (const float*)d_in[3];
    const float* temp   = (const float*)d_in[4];
    float* out = (float*)d_out;

    float *qkv, *qkvd, *invn, *aout;
    cudaGetSymbolAddress((void**)&qkv,  g_qkv);
    cudaGetSymbolAddress((void**)&qkvd, g_qkvd);
    cudaGetSymbolAddress((void**)&invn, g_invn);
    cudaGetSymbolAddress((void**)&aout, g_aout);

    // 1) 1x1 qkv conv: per-batch GEMM (1152 x 4096 x 384)
    {
        dim3 grid(HW_ / 128, C3_ / 128, B_);
        gemm_batched<<<grid, 256>>>(w_qkv, x, qkv, C3_, C_);
    }
    // 2) depthwise 3x3 fused with q/k L2 sumsq -> invn
    dwconv3x3_fused<<<B_ * C3_, 256>>>(qkv, w_dw, qkvd, invn);
    // 3) fused channel attention (scores + softmax + attn@v)
    attention<<<B_ * NH_, 256>>>(qkvd, invn, temp, aout);
    // 4) 1x1 proj: per-batch GEMM (384 x 4096 x 384)
    {
        dim3 grid(HW_ / 128, C_ / 128, B_);
        gemm_batched<<<grid, 256>>>(w_proj, aout, out, C_, C_);
    }
}

// round 14
// speedup vs baseline: 1.1027x; 1.1027x over previous
#include <cuda_runtime.h>
#include <cuda_bf16.h>
#include <math.h>
#include <stdint.h>

// ---------------------------------------------------------------------------
// MDTA on sm_103 (base target): mma.sync bf16-split GEMMs (tensor pipe via
// HMMA; tcgen05 unavailable through this toolchain's compute_103 PTX target)
// + fused dwconv/norm + attention.
// Shapes: b=16, c=384, h=w=64 (hw=4096), heads=8, d=48, 3c=1152
// ---------------------------------------------------------------------------

#define B_   16
#define C_   384
#define C3_  1152
#define HW_  4096
#define NH_  8
#define DH_  48

// Scratch (device globals; no allocation allowed)
__device__ float g_qkv [(size_t)B_ * C3_ * HW_];   // after 1x1 conv
__device__ float g_qkvd[(size_t)B_ * C3_ * HW_];   // after depthwise 3x3
__device__ float g_invn[B_ * 2 * C_];              // 1/max(||row||,eps)
__device__ float g_aout[(size_t)B_ * C_ * HW_];    // attention output (b,c,hw)

// bf16 hi/lo split operands
__device__ __nv_bfloat16 g_w3hi[C3_ * C_];
__device__ __nv_bfloat16 g_w3lo[C3_ * C_];
__device__ __nv_bfloat16 g_w1hi[C_ * C_];
__device__ __nv_bfloat16 g_w1lo[C_ * C_];
__device__ __nv_bfloat16 g_xthi[(size_t)B_ * HW_ * C_];  // x transposed [b][pix][c]
__device__ __nv_bfloat16 g_xtlo[(size_t)B_ * HW_ * C_];
__device__ __nv_bfloat16 g_athi[(size_t)B_ * HW_ * C_];  // aout transposed
__device__ __nv_bfloat16 g_atlo[(size_t)B_ * HW_ * C_];

__device__ __forceinline__ uint32_t smem_to_u32(const void* smem_ptr) {
    uint32_t addr;
    asm("{ .reg .u64 tmp; cvta.to.shared.u64 tmp, %1; cvt.u32.u64 %0, tmp; }"
        : "=r"(addr) : "l"(smem_ptr));
    return addr;
}

#define LDMATRIX_X4(r0, r1, r2, r3, addr) \
    asm volatile("ldmatrix.sync.aligned.m8n8.x4.shared.b16 {%0,%1,%2,%3}, [%4];" \
        : "=r"(r0), "=r"(r1), "=r"(r2), "=r"(r3) : "r"(addr))
#define LDMATRIX_X2(r0, r1, addr) \
    asm volatile("ldmatrix.sync.aligned.m8n8.x2.shared.b16 {%0,%1}, [%2];" \
        : "=r"(r0), "=r"(r1) : "r"(addr))
#define MMA_BF16(d, a, b) \
    asm volatile( \
        "mma.sync.aligned.m16n8k16.row.col.f32.bf16.bf16.f32 " \
        "{%0,%1,%2,%3}, {%4,%5,%6,%7}, {%8,%9}, {%0,%1,%2,%3};" \
        : "+f"((d)[0]), "+f"((d)[1]), "+f"((d)[2]), "+f"((d)[3]) \
        : "r"((a)[0]), "r"((a)[1]), "r"((a)[2]), "r"((a)[3]), \
          "r"((b)[0]), "r"((b)[1]))

// ===========================================================================
// mma.sync GEMM: out[b][m][pix] = sum_c W[m][c] * XT[b][pix][c]
// A = W [M][384] K-major bf16 hi/lo; B = XT [b][4096][384] K-major hi/lo.
// CTA tile 128(M) x 64(N) x 32(K); 8 warps (4x2), warp tile 32x32,
// 2x4 m16n8k16 atoms; 3 split-MMAs per atom. grid(HW/64, M/128, B_), 256 thr.
// smem row stride 40 bf16 (80B): conflict-free ldmatrix phases.
// ===========================================================================
#define SAS 40
__global__ __launch_bounds__(256) void mma_gemm(
    const __nv_bfloat16* __restrict__ Ahi, const __nv_bfloat16* __restrict__ Alo,
    const __nv_bfloat16* __restrict__ Bhi, const __nv_bfloat16* __restrict__ Blo,
    float* __restrict__ Cm, int M)
{
    constexpr int K = C_;   // 384
    __shared__ __nv_bfloat16 sAh[128 * SAS], sAl[128 * SAS];
    __shared__ __nv_bfloat16 sBh[64 * SAS],  sBl[64 * SAS];

    const int t    = threadIdx.x;
    const int wid  = t >> 5;
    const int lane = t & 31;
    const int m0   = blockIdx.y * 128;
    const int n0   = blockIdx.x * 64;
    const int bz   = blockIdx.z;
    const int warpM = wid & 3;      // 0..3 -> 32-row slab
    const int warpN = wid >> 2;     // 0..1 -> 32-col slab

    // loader mapping: 4 threads per row, 8 bf16 (one uint4) per thread
    const int lr  = t >> 2;          // 0..63
    const int seg = (t & 3) * 8;     // 0,8,16,24

    const __nv_bfloat16* gAh0 = Ahi + (size_t)(m0 + lr) * K + seg;
    const __nv_bfloat16* gAh1 = Ahi + (size_t)(m0 + lr + 64) * K + seg;
    const __nv_bfloat16* gAl0 = Alo + (size_t)(m0 + lr) * K + seg;
    const __nv_bfloat16* gAl1 = Alo + (size_t)(m0 + lr + 64) * K + seg;
    const __nv_bfloat16* gBh  = Bhi + ((size_t)bz * HW_ + n0 + lr) * K + seg;
    const __nv_bfloat16* gBl  = Blo + ((size_t)bz * HW_ + n0 + lr) * K + seg;

    float acc[2][4][4];
#pragma unroll
    for (int a = 0; a < 2; a++)
#pragma unroll
        for (int nb = 0; nb < 4; nb++)
#pragma unroll
            for (int i = 0; i < 4; i++) acc[a][nb][i] = 0.f;

    // precomputed ldmatrix shared addresses (vary only by kk per iter)
    const int arow0 = warpM * 32 + (lane & 15);
    const int acol  = (lane >> 4) * 8;
    const int brow  = warpN * 32 + (lane & 7);
    const int bcol  = ((lane >> 3) & 1) * 8;

    for (int k0 = 0; k0 < K; k0 += 32) {
        *(uint4*)&sAh[lr * SAS + seg]        = *(const uint4*)(gAh0 + k0);
        *(uint4*)&sAh[(lr + 64) * SAS + seg] = *(const uint4*)(gAh1 + k0);
        *(uint4*)&sAl[lr * SAS + seg]        = *(const uint4*)(gAl0 + k0);
        *(uint4*)&sAl[(lr + 64) * SAS + seg] = *(const uint4*)(gAl1 + k0);
        *(uint4*)&sBh[lr * SAS + seg]        = *(const uint4*)(gBh + k0);
        *(uint4*)&sBl[lr * SAS + seg]        = *(const uint4*)(gBl + k0);
        __syncthreads();

#pragma unroll
        for (int kk = 0; kk < 32; kk += 16) {
            uint32_t ah[2][4], al[2][4], bh[4][2], bl[4][2];
#pragma unroll
            for (int a = 0; a < 2; a++) {
                uint32_t adr_h = smem_to_u32(&sAh[(arow0 + a * 16) * SAS + kk + acol]);
                uint32_t adr_l = smem_to_u32(&sAl[(arow0 + a * 16) * SAS + kk + acol]);
                LDMATRIX_X4(ah[a][0], ah[a][1], ah[a][2], ah[a][3], adr_h);
                LDMATRIX_X4(al[a][0], al[a][1], al[a][2], al[a][3], adr_l);
            }
#pragma unroll
            for (int nb = 0; nb < 4; nb++) {
                uint32_t adr_h = smem_to_u32(&sBh[(brow + nb * 8) * SAS + kk + bcol]);
                uint32_t adr_l = smem_to_u32(&sBl[(brow + nb * 8) * SAS + kk + bcol]);
                LDMATRIX_X2(bh[nb][0], bh[nb][1], adr_h);
                LDMATRIX_X2(bl[nb][0], bl[nb][1], adr_l);
            }
#pragma unroll
            for (int a = 0; a < 2; a++)
#pragma unroll
                for (int nb = 0; nb < 4; nb++) {
                    MMA_BF16(acc[a][nb], ah[a], bh[nb]);
                    MMA_BF16(acc[a][nb], ah[a], bl[nb]);
                    MMA_BF16(acc[a][nb], al[a], bh[nb]);
                }
        }
        __syncthreads();
    }

    // epilogue: C fragment lane l -> rows {l/4, l/4+8}, cols (l%4)*2,+1
#pragma unroll
    for (int a = 0; a < 2; a++) {
        int row0 = m0 + warpM * 32 + a * 16 + (lane >> 2);
#pragma unroll
        for (int nb = 0; nb < 4; nb++) {
            int col = n0 + warpN * 32 + nb * 8 + (lane & 3) * 2;
            float* p0 = Cm + ((size_t)bz * M + row0) * HW_ + col;
            float* p1 = p0 + 8 * HW_;
            p0[0] = acc[a][nb][0];
            p0[1] = acc[a][nb][1];
            p1[0] = acc[a][nb][2];
            p1[1] = acc[a][nb][3];
        }
    }
}

// ===========================================================================
// fp32 -> bf16 hi/lo elementwise split (weights)
// ===========================================================================
__global__ __launch_bounds__(256) void split_w(
    const float* __restrict__ in, __nv_bfloat16* __restrict__ hi,
    __nv_bfloat16* __restrict__ lo, int n)
{
    int i = blockIdx.x * 256 + threadIdx.x;
    if (i >= n) return;
    float v = in[i];
    __nv_bfloat16 h = __float2bfloat16(v);
    hi[i] = h;
    lo[i] = __float2bfloat16(v - __bfloat162float(h));
}

// ===========================================================================
// Transpose [b][C][HW] fp32 -> [b][HW][C] bf16 hi/lo. 32x32 smem tiles.
// grid (HW/32, C/32, B), block (32, 8)
// ===========================================================================
__global__ __launch_bounds__(256) void transpose_split(
    const float* __restrict__ in, __nv_bfloat16* __restrict__ ohi,
    __nv_bfloat16* __restrict__ olo)
{
    __shared__ float tl[32][33];
    const int b  = blockIdx.z;
    const int p0 = blockIdx.x * 32;
    const int c0 = blockIdx.y * 32;
    const int tx = threadIdx.x, ty = threadIdx.y;
    const float* ib = in + (size_t)b * C_ * HW_;
#pragma unroll
    for (int i = 0; i < 4; i++)
        tl[ty + i * 8][tx] = ib[(size_t)(c0 + ty + i * 8) * HW_ + p0 + tx];
    __syncthreads();
#pragma unroll
    for (int i = 0; i < 4; i++) {
        float v = tl[tx][ty + i * 8];                  // in[c0+tx][p0+ty+i*8]
        __nv_bfloat16 h = __float2bfloat16(v);
        __nv_bfloat16 l = __float2bfloat16(v - __bfloat162float(h));
        size_t o = ((size_t)b * HW_ + p0 + ty + i * 8) * C_ + c0 + tx;
        ohi[o] = h;
        olo[o] = l;
    }
}

// ===========================================================================
// Depthwise 3x3 (SAME, groups=3c) fused with L2 sumsq for q/k channels.
// ===========================================================================
__global__ __launch_bounds__(256) void dwconv3x3_fused(
    const float* __restrict__ in, const float* __restrict__ wdw,
    float* __restrict__ out, float* __restrict__ invn)
{
    const int bc = blockIdx.x;            // b*1152 + c
    const int c  = bc % C3_;
    const int b  = bc / C3_;
    const int t  = threadIdx.x;

    __shared__ float tile[66 * 66];
    __shared__ float red[256];

    const float* ip = in  + ((size_t)bc << 12);
    float*       op = out + ((size_t)bc << 12);

    for (int i = t; i < 66 * 66; i += 256) {
        int yy = i / 66 - 1;
        int xx = i % 66 - 1;
        float v = 0.f;
        if (yy >= 0 && yy < 64 && xx >= 0 && xx < 64)
            v = ip[yy * 64 + xx];
        tile[i] = v;
    }
    float w0 = wdw[c * 9 + 0], w1 = wdw[c * 9 + 1], w2 = wdw[c * 9 + 2];
    float w3 = wdw[c * 9 + 3], w4 = wdw[c * 9 + 4], w5 = wdw[c * 9 + 5];
    float w6 = wdw[c * 9 + 6], w7 = wdw[c * 9 + 7], w8 = wdw[c * 9 + 8];
    __syncthreads();

    float ss = 0.f;
#pragma unroll
    for (int it = 0; it < 16; it++) {
        int pix = t + it * 256;
        int y = pix >> 6, x = pix & 63;
        const float* tp = &tile[y * 66 + x];
        float s;
        s =          tp[0]   * w0;
        s = fmaf(tp[1],   w1, s);
        s = fmaf(tp[2],   w2, s);
        s = fmaf(tp[66],  w3, s);
        s = fmaf(tp[67],  w4, s);
        s = fmaf(tp[68],  w5, s);
        s = fmaf(tp[132], w6, s);
        s = fmaf(tp[133], w7, s);
        s = fmaf(tp[134], w8, s);
        op[pix] = s;
        ss = fmaf(s, s, ss);
    }
    if (c < 2 * C_) {
        red[t] = ss;
        __syncthreads();
        for (int o = 128; o > 0; o >>= 1) {
            if (t < o) red[t] += red[t + o];
            __syncthreads();
        }
        if (t == 0)
            invn[b * 768 + c] = 1.f / fmaxf(sqrtf(red[0]), 1e-12f);
    }
}

// ===========================================================================
// Fused channel attention per (b, head).
// ===========================================================================
__global__ __launch_bounds__(256) void attention(
    const float* __restrict__ qkvd, const float* __restrict__ invn,
    const float* __restrict__ temp, float* __restrict__ aout)
{
    const int bh = blockIdx.x;
    const int b  = bh >> 3;
    const int hd = bh & 7;

    const float* q = qkvd + ((size_t)b * C3_ +            hd * DH_) * HW_;
    const float* k = qkvd + ((size_t)b * C3_ + C_  +      hd * DH_) * HW_;
    const float* v = qkvd + ((size_t)b * C3_ + 2 * C_ +   hd * DH_) * HW_;
    float*       o = aout + ((size_t)b * C_  +            hd * DH_) * HW_;

    __shared__ float pool[2 * 64 * 49];
    __shared__ float S[DH_ * 49];

    float* qs = pool;
    float* ks = pool + 64 * 49;

    const int t  = threadIdx.x;
    const int tx = t & 15;
    const int ty = t >> 4;

    float acc[3][3];
#pragma unroll
    for (int i = 0; i < 3; i++)
#pragma unroll
        for (int j = 0; j < 3; j++) acc[i][j] = 0.f;

    for (int n0 = 0; n0 < HW_; n0 += 64) {
        for (int i = t; i < DH_ * 64; i += 256) {
            int d = i >> 6, n = i & 63;
            qs[n * 49 + d] = q[(size_t)d * HW_ + n0 + n];
            ks[n * 49 + d] = k[(size_t)d * HW_ + n0 + n];
        }
        __syncthreads();
#pragma unroll 8
        for (int nn = 0; nn < 64; nn++) {
            float qa[3], kb[3];
#pragma unroll
            for (int i = 0; i < 3; i++) qa[i] = qs[nn * 49 + ty * 3 + i];
#pragma unroll
            for (int j = 0; j < 3; j++) kb[j] = ks[nn * 49 + tx * 3 + j];
#pragma unroll
            for (int i = 0; i < 3; i++)
#pragma unroll
                for (int j = 0; j < 3; j++) acc[i][j] = fmaf(qa[i], kb[j], acc[i][j]);
        }
        __syncthreads();
    }
    {
        const float tval = temp[hd];
        const float* iq = invn + b * 768 + hd * DH_;
        const float* ik = invn + b * 768 + C_ + hd * DH_;
#pragma unroll
        for (int i = 0; i < 3; i++) {
            int d = ty * 3 + i;
#pragma unroll
            for (int j = 0; j < 3; j++) {
                int e = tx * 3 + j;
                S[d * 49 + e] = acc[i][j] * iq[d] * ik[e] * tval;
            }
        }
    }
    __syncthreads();

    if (t < DH_) {
        float m = -1e30f;
#pragma unroll
        for (int e = 0; e < DH_; e++) m = fmaxf(m, S[t * 49 + e]);
        float sum = 0.f;
#pragma unroll
        for (int e = 0; e < DH_; e++) {
            float ex = expf(S[t * 49 + e] - m);
            S[t * 49 + e] = ex;
            sum += ex;
        }
        float inv = 1.f / sum;
#pragma unroll
        for (int e = 0; e < DH_; e++) S[t * 49 + e] *= inv;
    }
    __syncthreads();

    float* vs = pool;
    for (int n0 = 0; n0 < HW_; n0 += 64) {
        for (int i = t; i < DH_ * 64; i += 256) {
            int e = i >> 6, n = i & 63;
            vs[e * 68 + n] = v[(size_t)e * HW_ + n0 + n];
        }
        __syncthreads();

        float acc2[3][4];
#pragma unroll
        for (int i = 0; i < 3; i++)
#pragma unroll
            for (int j = 0; j < 4; j++) acc2[i][j] = 0.f;

#pragma unroll 8
        for (int e = 0; e < DH_; e++) {
            float a0 = S[(ty * 3 + 0) * 49 + e];
            float a1 = S[(ty * 3 + 1) * 49 + e];
            float a2 = S[(ty * 3 + 2) * 49 + e];
            float4 vv = *(const float4*)&vs[e * 68 + tx * 4];
            float vb[4] = {vv.x, vv.y, vv.z, vv.w};
#pragma unroll
            for (int j = 0; j < 4; j++) {
                acc2[0][j] = fmaf(a0, vb[j], acc2[0][j]);
                acc2[1][j] = fmaf(a1, vb[j], acc2[1][j]);
                acc2[2][j] = fmaf(a2, vb[j], acc2[2][j]);
            }
        }
#pragma unroll
        for (int i = 0; i < 3; i++) {
            float4 cv = make_float4(acc2[i][0], acc2[i][1], acc2[i][2], acc2[i][3]);
            *(float4*)&o[(size_t)(ty * 3 + i) * HW_ + n0 + tx * 4] = cv;
        }
        __syncthreads();
    }
}

// ---------------------------------------------------------------------------
extern "C" void kernel_launch(void* const* d_in, const int* in_sizes, int n_in,
                              void* d_out, int out_size)
{
    const float* x      = (const float*)d_in[0];
    const float* w_qkv  = (const float*)d_in[1];
    const float* w_dw   = (const float*)d_in[2];
    const float* w_proj = (const float*)d_in[3];
    const float* temp   = (const float*)d_in[4];
    float* out = (float*)d_out;

    float *qkv, *qkvd, *invn, *aout;
    __nv_bfloat16 *w3hi, *w3lo, *w1hi, *w1lo, *xthi, *xtlo, *athi, *atlo;
    cudaGetSymbolAddress((void**)&qkv,  g_qkv);
    cudaGetSymbolAddress((void**)&qkvd, g_qkvd);
    cudaGetSymbolAddress((void**)&invn, g_invn);
    cudaGetSymbolAddress((void**)&aout, g_aout);
    cudaGetSymbolAddress((void**)&w3hi, g_w3hi);
    cudaGetSymbolAddress((void**)&w3lo, g_w3lo);
    cudaGetSymbolAddress((void**)&w1hi, g_w1hi);
    cudaGetSymbolAddress((void**)&w1lo, g_w1lo);
    cudaGetSymbolAddress((void**)&xthi, g_xthi);
    cudaGetSymbolAddress((void**)&xtlo, g_xtlo);
    cudaGetSymbolAddress((void**)&athi, g_athi);
    cudaGetSymbolAddress((void**)&atlo, g_atlo);

    // 0) weight splits + x transpose/split
    split_w<<<(C3_ * C_ + 255) / 256, 256>>>(w_qkv, w3hi, w3lo, C3_ * C_);
    split_w<<<(C_ * C_ + 255) / 256, 256>>>(w_proj, w1hi, w1lo, C_ * C_);
    {
        dim3 grid(HW_ / 32, C_ / 32, B_);
        transpose_split<<<grid, dim3(32, 8)>>>(x, xthi, xtlo);
    }
    // 1) qkv 1x1 conv on tensor pipe (mma.sync bf16 split)
    {
        dim3 grid(HW_ / 64, C3_ / 128, B_);
        mma_gemm<<<grid, 256>>>(w3hi, w3lo, xthi, xtlo, qkv, C3_);
    }
    // 2) depthwise 3x3 fused with q/k L2 sumsq
    dwconv3x3_fused<<<B_ * C3_, 256>>>(qkv, w_dw, qkvd, invn);
    // 3) channel attention
    attention<<<B_ * NH_, 256>>>(qkvd, invn, temp, aout);
    // 4) aout transpose/split + proj
    {
        dim3 grid(HW_ / 32, C_ / 32, B_);
        transpose_split<<<grid, dim3(32, 8)>>>(aout, athi, atlo);
    }
    {
        dim3 grid(HW_ / 64, C_ / 128, B_);
        mma_gemm<<<grid, 256>>>(w1hi, w1lo, athi, atlo, out, C_);
    }
}

// round 17
// speedup vs baseline: 1.5663x; 1.4205x over previous
#include <cuda_runtime.h>
#include <cuda_bf16.h>
#include <math.h>
#include <stdint.h>

// ---------------------------------------------------------------------------
// MDTA on sm_103 (base target): cp.async-pipelined mma.sync bf16-split GEMMs
// + fused dwconv/norm + 8x-parallel attention.
// Shapes: b=16, c=384, h=w=64 (hw=4096), heads=8, d=48, 3c=1152
// ---------------------------------------------------------------------------

#define B_   16
#define C_   384
#define C3_  1152
#define HW_  4096
#define NH_  8
#define DH_  48

// Scratch (device globals; no allocation allowed)
__device__ float g_qkv [(size_t)B_ * C3_ * HW_];
__device__ float g_qkvd[(size_t)B_ * C3_ * HW_];
__device__ float g_invn[B_ * 2 * C_];
__device__ float g_aout[(size_t)B_ * C_ * HW_];
__device__ float g_part[(size_t)B_ * NH_ * 8 * DH_ * DH_];  // partial scores
__device__ float g_Smat[(size_t)B_ * NH_ * DH_ * DH_];      // softmaxed attn

// bf16 hi/lo split operands
__device__ __nv_bfloat16 g_w3hi[C3_ * C_];
__device__ __nv_bfloat16 g_w3lo[C3_ * C_];
__device__ __nv_bfloat16 g_w1hi[C_ * C_];
__device__ __nv_bfloat16 g_w1lo[C_ * C_];
__device__ __nv_bfloat16 g_xthi[(size_t)B_ * HW_ * C_];
__device__ __nv_bfloat16 g_xtlo[(size_t)B_ * HW_ * C_];
__device__ __nv_bfloat16 g_athi[(size_t)B_ * HW_ * C_];
__device__ __nv_bfloat16 g_atlo[(size_t)B_ * HW_ * C_];

__device__ __forceinline__ uint32_t smem_to_u32(const void* smem_ptr) {
    uint32_t addr;
    asm("{ .reg .u64 tmp; cvta.to.shared.u64 tmp, %1; cvt.u32.u64 %0, tmp; }"
        : "=r"(addr) : "l"(smem_ptr));
    return addr;
}

#define LDMATRIX_X4(r0, r1, r2, r3, addr) \
    asm volatile("ldmatrix.sync.aligned.m8n8.x4.shared.b16 {%0,%1,%2,%3}, [%4];" \
        : "=r"(r0), "=r"(r1), "=r"(r2), "=r"(r3) : "r"(addr))
#define LDMATRIX_X2(r0, r1, addr) \
    asm volatile("ldmatrix.sync.aligned.m8n8.x2.shared.b16 {%0,%1}, [%2];" \
        : "=r"(r0), "=r"(r1) : "r"(addr))
#define MMA_BF16(d, a, b) \
    asm volatile( \
        "mma.sync.aligned.m16n8k16.row.col.f32.bf16.bf16.f32 " \
        "{%0,%1,%2,%3}, {%4,%5,%6,%7}, {%8,%9}, {%0,%1,%2,%3};" \
        : "+f"((d)[0]), "+f"((d)[1]), "+f"((d)[2]), "+f"((d)[3]) \
        : "r"((a)[0]), "r"((a)[1]), "r"((a)[2]), "r"((a)[3]), \
          "r"((b)[0]), "r"((b)[1]))
#define CP16(saddr, gptr) \
    asm volatile("cp.async.cg.shared.global [%0], [%1], 16;" \
        :: "r"(saddr), "l"(gptr) : "memory")
#define CP_COMMIT() asm volatile("cp.async.commit_group;" ::: "memory")
#define CP_WAIT1()  asm volatile("cp.async.wait_group 1;" ::: "memory")
#define CP_WAIT0()  asm volatile("cp.async.wait_group 0;" ::: "memory")

// ===========================================================================
// cp.async double-buffered mma.sync GEMM.
// out[b][m][pix] = sum_c W[m][c] * XT[b][pix][c]
// CTA tile 128(M) x 64(N) x 32(K); 8 warps (4x2), warp tile 32x32.
// Dynamic smem: 2 buffers x 30720 B (sAh 10240 | sAl 10240 | sBh 5120 | sBl 5120)
// ===========================================================================
#define SAS  40
#define BUFB 30720
#define OAL  10240
#define OBH  20480
#define OBL  25600
__global__ __launch_bounds__(256, 2) void mma_gemm(
    const __nv_bfloat16* __restrict__ Ahi, const __nv_bfloat16* __restrict__ Alo,
    const __nv_bfloat16* __restrict__ Bhi, const __nv_bfloat16* __restrict__ Blo,
    float* __restrict__ Cm, int M)
{
    constexpr int K = C_;          // 384; 12 k-tiles of 32
    extern __shared__ __nv_bfloat16 smem[];
    const uint32_t sb = smem_to_u32(smem);

    const int t    = threadIdx.x;
    const int wid  = t >> 5;
    const int lane = t & 31;
    const int m0   = blockIdx.y * 128;
    const int n0   = blockIdx.x * 64;
    const int bz   = blockIdx.z;
    const int warpM = wid & 3;
    const int warpN = wid >> 2;

    const int lr  = t >> 2;          // 0..63
    const int seg = (t & 3) * 8;     // 0,8,16,24

    const __nv_bfloat16* gAh0 = Ahi + (size_t)(m0 + lr) * K + seg;
    const __nv_bfloat16* gAh1 = Ahi + (size_t)(m0 + lr + 64) * K + seg;
    const __nv_bfloat16* gAl0 = Alo + (size_t)(m0 + lr) * K + seg;
    const __nv_bfloat16* gAl1 = Alo + (size_t)(m0 + lr + 64) * K + seg;
    const __nv_bfloat16* gBh  = Bhi + ((size_t)bz * HW_ + n0 + lr) * K + seg;
    const __nv_bfloat16* gBl  = Blo + ((size_t)bz * HW_ + n0 + lr) * K + seg;

    const uint32_t dA0 = (uint32_t)((lr * SAS + seg) * 2);
    const uint32_t dA1 = (uint32_t)(((lr + 64) * SAS + seg) * 2);

#define ISSUE(buf, k0) do { \
    uint32_t _b = sb + (uint32_t)(buf) * BUFB; \
    CP16(_b +        dA0, gAh0 + (k0)); \
    CP16(_b +        dA1, gAh1 + (k0)); \
    CP16(_b + OAL  + dA0, gAl0 + (k0)); \
    CP16(_b + OAL  + dA1, gAl1 + (k0)); \
    CP16(_b + OBH  + dA0, gBh  + (k0)); \
    CP16(_b + OBL  + dA0, gBl  + (k0)); \
    CP_COMMIT(); \
} while (0)

    float acc[2][4][4];
#pragma unroll
    for (int a = 0; a < 2; a++)
#pragma unroll
        for (int nb = 0; nb < 4; nb++)
#pragma unroll
            for (int i = 0; i < 4; i++) acc[a][nb][i] = 0.f;

    const int arow0 = warpM * 32 + (lane & 15);
    const int acol  = (lane >> 4) * 8;
    const int brow  = warpN * 32 + (lane & 7);
    const int bcol  = ((lane >> 3) & 1) * 8;

    ISSUE(0, 0);

    for (int c = 0; c < 12; c++) {
        if (c + 1 < 12) {
            ISSUE((c + 1) & 1, (c + 1) * 32);
            CP_WAIT1();
        } else {
            CP_WAIT0();
        }
        __syncthreads();

        const uint32_t base = sb + (uint32_t)(c & 1) * BUFB;
#pragma unroll
        for (int kk = 0; kk < 32; kk += 16) {
            uint32_t ah[2][4], al[2][4], bh[4][2], bl[4][2];
#pragma unroll
            for (int a = 0; a < 2; a++) {
                uint32_t ro = ((arow0 + a * 16) * SAS + kk + acol) * 2;
                LDMATRIX_X4(ah[a][0], ah[a][1], ah[a][2], ah[a][3], base + ro);
                LDMATRIX_X4(al[a][0], al[a][1], al[a][2], al[a][3], base + OAL + ro);
            }
#pragma unroll
            for (int nb = 0; nb < 4; nb++) {
                uint32_t ro = ((brow + nb * 8) * SAS + kk + bcol) * 2;
                LDMATRIX_X2(bh[nb][0], bh[nb][1], base + OBH + ro);
                LDMATRIX_X2(bl[nb][0], bl[nb][1], base + OBL + ro);
            }
#pragma unroll
            for (int a = 0; a < 2; a++)
#pragma unroll
                for (int nb = 0; nb < 4; nb++) {
                    MMA_BF16(acc[a][nb], ah[a], bh[nb]);
                    MMA_BF16(acc[a][nb], ah[a], bl[nb]);
                    MMA_BF16(acc[a][nb], al[a], bh[nb]);
                }
        }
        __syncthreads();
    }
#undef ISSUE

#pragma unroll
    for (int a = 0; a < 2; a++) {
        int row0 = m0 + warpM * 32 + a * 16 + (lane >> 2);
#pragma unroll
        for (int nb = 0; nb < 4; nb++) {
            int col = n0 + warpN * 32 + nb * 8 + (lane & 3) * 2;
            float* p0 = Cm + ((size_t)bz * M + row0) * HW_ + col;
            float* p1 = p0 + 8 * HW_;
            p0[0] = acc[a][nb][0];
            p0[1] = acc[a][nb][1];
            p1[0] = acc[a][nb][2];
            p1[1] = acc[a][nb][3];
        }
    }
}

// ===========================================================================
// fp32 -> bf16 hi/lo split (weights)
// ===========================================================================
__global__ __launch_bounds__(256) void split_w(
    const float* __restrict__ in, __nv_bfloat16* __restrict__ hi,
    __nv_bfloat16* __restrict__ lo, int n)
{
    int i = blockIdx.x * 256 + threadIdx.x;
    if (i >= n) return;
    float v = in[i];
    __nv_bfloat16 h = __float2bfloat16(v);
    hi[i] = h;
    lo[i] = __float2bfloat16(v - __bfloat162float(h));
}

// ===========================================================================
// Transpose [b][C][HW] fp32 -> [b][HW][C] bf16 hi/lo.
// ===========================================================================
__global__ __launch_bounds__(256) void transpose_split(
    const float* __restrict__ in, __nv_bfloat16* __restrict__ ohi,
    __nv_bfloat16* __restrict__ olo)
{
    __shared__ float tl[32][33];
    const int b  = blockIdx.z;
    const int p0 = blockIdx.x * 32;
    const int c0 = blockIdx.y * 32;
    const int tx = threadIdx.x, ty = threadIdx.y;
    const float* ib = in + (size_t)b * C_ * HW_;
#pragma unroll
    for (int i = 0; i < 4; i++)
        tl[ty + i * 8][tx] = ib[(size_t)(c0 + ty + i * 8) * HW_ + p0 + tx];
    __syncthreads();
#pragma unroll
    for (int i = 0; i < 4; i++) {
        float v = tl[tx][ty + i * 8];
        __nv_bfloat16 h = __float2bfloat16(v);
        __nv_bfloat16 l = __float2bfloat16(v - __bfloat162float(h));
        size_t o = ((size_t)b * HW_ + p0 + ty + i * 8) * C_ + c0 + tx;
        ohi[o] = h;
        olo[o] = l;
    }
}

// ===========================================================================
// Depthwise 3x3 (SAME) fused with L2 sumsq for q/k channels.
// ===========================================================================
__global__ __launch_bounds__(256) void dwconv3x3_fused(
    const float* __restrict__ in, const float* __restrict__ wdw,
    float* __restrict__ out, float* __restrict__ invn)
{
    const int bc = blockIdx.x;
    const int c  = bc % C3_;
    const int b  = bc / C3_;
    const int t  = threadIdx.x;

    __shared__ float tile[66 * 66];
    __shared__ float red[256];

    const float* ip = in  + ((size_t)bc << 12);
    float*       op = out + ((size_t)bc << 12);

    for (int i = t; i < 66 * 66; i += 256) {
        int yy = i / 66 - 1;
        int xx = i % 66 - 1;
        float v = 0.f;
        if (yy >= 0 && yy < 64 && xx >= 0 && xx < 64)
            v = ip[yy * 64 + xx];
        tile[i] = v;
    }
    float w0 = wdw[c * 9 + 0], w1 = wdw[c * 9 + 1], w2 = wdw[c * 9 + 2];
    float w3 = wdw[c * 9 + 3], w4 = wdw[c * 9 + 4], w5 = wdw[c * 9 + 5];
    float w6 = wdw[c * 9 + 6], w7 = wdw[c * 9 + 7], w8 = wdw[c * 9 + 8];
    __syncthreads();

    float ss = 0.f;
#pragma unroll
    for (int it = 0; it < 16; it++) {
        int pix = t + it * 256;
        int y = pix >> 6, x = pix & 63;
        const float* tp = &tile[y * 66 + x];
        float s;
        s =          tp[0]   * w0;
        s = fmaf(tp[1],   w1, s);
        s = fmaf(tp[2],   w2, s);
        s = fmaf(tp[66],  w3, s);
        s = fmaf(tp[67],  w4, s);
        s = fmaf(tp[68],  w5, s);
        s = fmaf(tp[132], w6, s);
        s = fmaf(tp[133], w7, s);
        s = fmaf(tp[134], w8, s);
        op[pix] = s;
        ss = fmaf(s, s, ss);
    }
    if (c < 2 * C_) {
        red[t] = ss;
        __syncthreads();
        for (int o = 128; o > 0; o >>= 1) {
            if (t < o) red[t] += red[t + o];
            __syncthreads();
        }
        if (t == 0)
            invn[b * 768 + c] = 1.f / fmaxf(sqrtf(red[0]), 1e-12f);
    }
}

// ===========================================================================
// Attention stage A: partial scores over a 512-pixel chunk.
// grid (128, 8), 256 threads. part[(bh*8+chk)*2304 + d*48 + e]
// ===========================================================================
__global__ __launch_bounds__(256) void attn_scores(
    const float* __restrict__ qkvd, float* __restrict__ part)
{
    const int bh  = blockIdx.x;
    const int chk = blockIdx.y;
    const int b   = bh >> 3;
    const int hd  = bh & 7;

    const float* q = qkvd + ((size_t)b * C3_ +       hd * DH_) * HW_;
    const float* k = qkvd + ((size_t)b * C3_ + C_ +  hd * DH_) * HW_;

    __shared__ float pool[2 * 64 * 49];
    float* qs = pool;
    float* ks = pool + 64 * 49;

    const int t  = threadIdx.x;
    const int tx = t & 15;
    const int ty = t >> 4;

    float acc[3][3];
#pragma unroll
    for (int i = 0; i < 3; i++)
#pragma unroll
        for (int j = 0; j < 3; j++) acc[i][j] = 0.f;

    const int nbeg = chk * 512;
    for (int n0 = nbeg; n0 < nbeg + 512; n0 += 64) {
        for (int i = t; i < DH_ * 64; i += 256) {
            int d = i >> 6, n = i & 63;
            qs[n * 49 + d] = q[(size_t)d * HW_ + n0 + n];
            ks[n * 49 + d] = k[(size_t)d * HW_ + n0 + n];
        }
        __syncthreads();
#pragma unroll 8
        for (int nn = 0; nn < 64; nn++) {
            float qa[3], kb[3];
#pragma unroll
            for (int i = 0; i < 3; i++) qa[i] = qs[nn * 49 + ty * 3 + i];
#pragma unroll
            for (int j = 0; j < 3; j++) kb[j] = ks[nn * 49 + tx * 3 + j];
#pragma unroll
            for (int i = 0; i < 3; i++)
#pragma unroll
                for (int j = 0; j < 3; j++) acc[i][j] = fmaf(qa[i], kb[j], acc[i][j]);
        }
        __syncthreads();
    }

    float* po = part + ((size_t)(bh * 8 + chk)) * (DH_ * DH_);
#pragma unroll
    for (int i = 0; i < 3; i++)
#pragma unroll
        for (int j = 0; j < 3; j++)
            po[(ty * 3 + i) * DH_ + tx * 3 + j] = acc[i][j];
}

// ===========================================================================
// Attention stage B: reduce partials, scale, softmax. grid 128, 64 threads.
// ===========================================================================
__global__ __launch_bounds__(64) void attn_softmax(
    const float* __restrict__ part, const float* __restrict__ invn,
    const float* __restrict__ temp, float* __restrict__ Smat)
{
    const int bh = blockIdx.x;
    const int b  = bh >> 3;
    const int hd = bh & 7;
    const int d  = threadIdx.x;
    if (d >= DH_) return;

    const float iqd  = invn[b * 768 + hd * DH_ + d];
    const float tval = temp[hd];
    const float* ik  = invn + b * 768 + C_ + hd * DH_;

    float row[DH_];
#pragma unroll
    for (int e = 0; e < DH_; e++) {
        float s = 0.f;
#pragma unroll
        for (int c = 0; c < 8; c++)
            s += part[((size_t)(bh * 8 + c)) * (DH_ * DH_) + d * DH_ + e];
        row[e] = s * iqd * ik[e] * tval;
    }
    float m = -1e30f;
#pragma unroll
    for (int e = 0; e < DH_; e++) m = fmaxf(m, row[e]);
    float sum = 0.f;
#pragma unroll
    for (int e = 0; e < DH_; e++) {
        row[e] = expf(row[e] - m);
        sum += row[e];
    }
    float inv = 1.f / sum;
    float* so = Smat + (size_t)bh * (DH_ * DH_) + d * DH_;
#pragma unroll
    for (int e = 0; e < DH_; e++) so[e] = row[e] * inv;
}

// ===========================================================================
// Attention stage C: out[:,chunk] = S @ v[:,chunk]. grid (128, 8), 256 thr.
// ===========================================================================
__global__ __launch_bounds__(256) void attn_av(
    const float* __restrict__ qkvd, const float* __restrict__ Smat,
    float* __restrict__ aout)
{
    const int bh  = blockIdx.x;
    const int chk = blockIdx.y;
    const int b   = bh >> 3;
    const int hd  = bh & 7;

    const float* v = qkvd + ((size_t)b * C3_ + 2 * C_ + hd * DH_) * HW_;
    float*       o = aout + ((size_t)b * C_  +          hd * DH_) * HW_;

    __shared__ float S[DH_ * 49];
    __shared__ float vs[DH_ * 68];

    const int t  = threadIdx.x;
    const int tx = t & 15;
    const int ty = t >> 4;

    const float* si = Smat + (size_t)bh * (DH_ * DH_);
    for (int i = t; i < DH_ * DH_; i += 256) {
        int d = i / DH_, e = i % DH_;
        S[d * 49 + e] = si[i];
    }
    __syncthreads();

    const int nbeg = chk * 512;
    for (int n0 = nbeg; n0 < nbeg + 512; n0 += 64) {
        for (int i = t; i < DH_ * 64; i += 256) {
            int e = i >> 6, n = i & 63;
            vs[e * 68 + n] = v[(size_t)e * HW_ + n0 + n];
        }
        __syncthreads();

        float acc2[3][4];
#pragma unroll
        for (int i = 0; i < 3; i++)
#pragma unroll
            for (int j = 0; j < 4; j++) acc2[i][j] = 0.f;

#pragma unroll 8
        for (int e = 0; e < DH_; e++) {
            float a0 = S[(ty * 3 + 0) * 49 + e];
            float a1 = S[(ty * 3 + 1) * 49 + e];
            float a2 = S[(ty * 3 + 2) * 49 + e];
            float4 vv = *(const float4*)&vs[e * 68 + tx * 4];
            float vb[4] = {vv.x, vv.y, vv.z, vv.w};
#pragma unroll
            for (int j = 0; j < 4; j++) {
                acc2[0][j] = fmaf(a0, vb[j], acc2[0][j]);
                acc2[1][j] = fmaf(a1, vb[j], acc2[1][j]);
                acc2[2][j] = fmaf(a2, vb[j], acc2[2][j]);
            }
        }
#pragma unroll
        for (int i = 0; i < 3; i++) {
            float4 cv = make_float4(acc2[i][0], acc2[i][1], acc2[i][2], acc2[i][3]);
            *(float4*)&o[(size_t)(ty * 3 + i) * HW_ + n0 + tx * 4] = cv;
        }
        __syncthreads();
    }
}

// ---------------------------------------------------------------------------
extern "C" void kernel_launch(void* const* d_in, const int* in_sizes, int n_in,
                              void* d_out, int out_size)
{
    const float* x      = (const float*)d_in[0];
    const float* w_qkv  = (const float*)d_in[1];
    const float* w_dw   = (const float*)d_in[2];
    const float* w_proj = (const float*)d_in[3];
    const float* temp   = (const float*)d_in[4];
    float* out = (float*)d_out;

    float *qkv, *qkvd, *invn, *aout, *part, *Smat;
    __nv_bfloat16 *w3hi, *w3lo, *w1hi, *w1lo, *xthi, *xtlo, *athi, *atlo;
    cudaGetSymbolAddress((void**)&qkv,  g_qkv);
    cudaGetSymbolAddress((void**)&qkvd, g_qkvd);
    cudaGetSymbolAddress((void**)&invn, g_invn);
    cudaGetSymbolAddress((void**)&aout, g_aout);
    cudaGetSymbolAddress((void**)&part, g_part);
    cudaGetSymbolAddress((void**)&Smat, g_Smat);
    cudaGetSymbolAddress((void**)&w3hi, g_w3hi);
    cudaGetSymbolAddress((void**)&w3lo, g_w3lo);
    cudaGetSymbolAddress((void**)&w1hi, g_w1hi);
    cudaGetSymbolAddress((void**)&w1lo, g_w1lo);
    cudaGetSymbolAddress((void**)&xthi, g_xthi);
    cudaGetSymbolAddress((void**)&xtlo, g_xtlo);
    cudaGetSymbolAddress((void**)&athi, g_athi);
    cudaGetSymbolAddress((void**)&atlo, g_atlo);

    cudaFuncSetAttribute(mma_gemm, cudaFuncAttributeMaxDynamicSharedMemorySize,
                         2 * BUFB);

    // 0) weight splits + x transpose/split
    split_w<<<(C3_ * C_ + 255) / 256, 256>>>(w_qkv, w3hi, w3lo, C3_ * C_);
    split_w<<<(C_ * C_ + 255) / 256, 256>>>(w_proj, w1hi, w1lo, C_ * C_);
    {
        dim3 grid(HW_ / 32, C_ / 32, B_);
        transpose_split<<<grid, dim3(32, 8)>>>(x, xthi, xtlo);
    }
    // 1) qkv 1x1 conv (pipelined tensor-pipe GEMM)
    {
        dim3 grid(HW_ / 64, C3_ / 128, B_);
        mma_gemm<<<grid, 256, 2 * BUFB>>>(w3hi, w3lo, xthi, xtlo, qkv, C3_);
    }
    // 2) depthwise 3x3 fused with q/k L2 sumsq
    dwconv3x3_fused<<<B_ * C3_, 256>>>(qkv, w_dw, qkvd, invn);
    // 3) attention: partial scores -> softmax -> A@V
    attn_scores<<<dim3(B_ * NH_, 8), 256>>>(qkvd, part);
    attn_softmax<<<B_ * NH_, 64>>>(part, invn, temp, Smat);
    attn_av<<<dim3(B_ * NH_, 8), 256>>>(qkvd, Smat, aout);
    // 4) aout transpose/split + proj
    {
        dim3 grid(HW_ / 32, C_ / 32, B_);
        transpose_split<<<grid, dim3(32, 8)>>>(aout, athi, atlo);
    }
    {
        dim3 grid(HW_ / 64, C_ / 128, B_);
        mma_gemm<<<grid, 256, 2 * BUFB>>>(w1hi, w1lo, athi, atlo, out, C_);
    }
}